// round 4
// baseline (speedup 1.0000x reference)
#include <cuda_runtime.h>
#include <math.h>
#include <stdint.h>

// Problem constants
#define BB 16          // batch
#define SS 4096        // sequence
#define DD 64          // head dim
#define HH 8           // n_hashes
#define NB 64          // buckets per hash
#define NROT 32        // n_buckets/2 rotation outputs
#define TBK 512        // total buckets per batch (HH*NB)
#define CHUNKS 512     // sorted chunks per batch
#define BSZ 64         // bucket/chunk size
#define KEYS 128       // keys per chunk (own + look-back)
#define TOT (HH*SS)    // 32768 sorted entries per batch

// ---------------- scratch (device globals; no allocs allowed) ----------------
__device__ int   g_buckets[BB*TOT];          // bucket id (incl. h*64 offset) per (b,h,t)
__device__ int   g_hist[BB*TBK];
__device__ int   g_off[BB*TBK];
__device__ int   g_tick[BB*TOT];             // sorted tickers (h*S + t)
__device__ float g_logits[BB*TOT];           // lse per (b, ticker)
__device__ float g_o[(size_t)BB*TOT*DD];     // per-hash outputs, 128 MB

// ---------------- kernel 0: zero histogram (graph-replay determinism) --------
__global__ void k_zero() {
    int i = blockIdx.x * blockDim.x + threadIdx.x;
    if (i < BB*TBK) g_hist[i] = 0;
}

// ---------------- kernel 1: LSH hashing --------------------------------------
// rotated[b,h,t,i] = sum_f qk[b,t,f]*rot[f,h,i], SINGLE sequential FMA chain
// over f per output (matches sgemm k-loop rounding). 4 chains interleaved for ILP.
__global__ void __launch_bounds__(256) k_hash(const float* __restrict__ qk,
                                              const float* __restrict__ rot) {
    extern __shared__ float srot[];          // [D][H][NROT] = 16384 floats
    for (int i = threadIdx.x; i < DD*HH*NROT; i += blockDim.x) srot[i] = rot[i];
    __syncthreads();

    int g = blockIdx.x * blockDim.x + threadIdx.x;  // global token (b*S + t)
    int b = g >> 12;
    int t = g & (SS - 1);

    float q[DD];
    const float4* qp = (const float4*)(qk + (size_t)g * DD);
#pragma unroll
    for (int i = 0; i < 16; i++) {
        float4 x = qp[i];
        q[4*i] = x.x; q[4*i+1] = x.y; q[4*i+2] = x.z; q[4*i+3] = x.w;
    }

    for (int h = 0; h < HH; h++) {
        float bv = -INFINITY; int bi = 0;
        const float* rbase = srot + h * NROT;
        for (int i0 = 0; i0 < NROT; i0 += 4) {
            // 4 independent sequential chains (ILP without changing rounding)
            float s0 = 0.f, s1 = 0.f, s2 = 0.f, s3 = 0.f;
            const float* rp = rbase + i0;
#pragma unroll
            for (int f = 0; f < DD; f++) {
                float qf = q[f];
                const float* rr = rp + f * (HH*NROT);
                s0 = fmaf(qf, rr[0], s0);
                s1 = fmaf(qf, rr[1], s1);
                s2 = fmaf(qf, rr[2], s2);
                s3 = fmaf(qf, rr[3], s3);
            }
            float accs[4] = {s0, s1, s2, s3};
#pragma unroll
            for (int u = 0; u < 4; u++) {
                int i = i0 + u;
                float acc = accs[u];
                // argmax-first == max with tie -> smaller index
                if (acc > bv || (acc == bv && i < bi)) { bv = acc; bi = i; }
                float na = -acc; int ni = NROT + i;
                if (na > bv || (na == bv && ni < bi)) { bv = na; bi = ni; }
            }
        }
        int bucket = bi + h * NB;
        g_buckets[b*TOT + h*SS + t] = bucket;
        atomicAdd(&g_hist[b*TBK + bucket], 1);
    }
}

// ---------------- kernel 2: exclusive scan of histogram (per batch) ----------
__global__ void k_scan() {
    __shared__ int s[TBK];
    int b = blockIdx.x, t = threadIdx.x;
    int myv = g_hist[b*TBK + t];
    s[t] = myv;
    __syncthreads();
    for (int o = 1; o < TBK; o <<= 1) {
        int v = (t >= o) ? s[t - o] : 0;
        __syncthreads();
        s[t] += v;
        __syncthreads();
    }
    g_off[b*TBK + t] = s[t] - myv;
}

// ---------------- kernel 3: counting-sort scatter (stable in t) --------------
__global__ void k_scatter() {
    int idx = blockIdx.x * blockDim.x + threadIdx.x;   // b*TBK + bucket
    if (idx >= BB*TBK) return;
    int b = idx / TBK, bucket = idx % TBK;
    int h = bucket >> 6;                 // bucket range determines hash round
    const int4* bp = (const int4*)(g_buckets + b*TOT + h*SS);
    int off = g_off[idx];
    int* out = g_tick + b*TOT;
    int base = h * SS;
    for (int t4 = 0; t4 < SS/4; t4++) {
        int4 v = bp[t4];
        int t = t4 * 4;
        if (v.x == bucket) out[off++] = base + t;
        if (v.y == bucket) out[off++] = base + t + 1;
        if (v.z == bucket) out[off++] = base + t + 2;
        if (v.w == bucket) out[off++] = base + t + 3;
    }
}

// ---------------- kernel 4: chunked attention --------------------------------
// One block per (chunk, batch). 64 queries x 128 keys x D=64.
// Shared: Q[64][65] raw, K̂[128][65], V[128][65], S[64][129], positions/tickers.
#define QSTR 65
#define KSTR 65
#define SSTR 129
#define ATT_SMEM ((BSZ*QSTR + KEYS*KSTR + KEYS*KSTR + BSZ*SSTR)*4 + KEYS*4 + BSZ*4)

__global__ void __launch_bounds__(128, 1) k_attn(const float* __restrict__ qk,
                                                 const float* __restrict__ v) {
    extern __shared__ char smraw[];
    float* Qs  = (float*)smraw;                   // raw q, queries only
    float* Ks  = Qs + BSZ*QSTR;                   // normalized k
    float* Vs  = Ks + KEYS*KSTR;
    float* Sm  = Vs + KEYS*KSTR;                  // dots -> probs
    int*   tkt = (int*)(Sm + BSZ*SSTR);           // key positions (t)
    int*   qtk = tkt + KEYS;                      // query tickers (h*S+t)

    int c = blockIdx.x, b = blockIdx.y;
    int tid = threadIdx.x;

    // ---- load: thread r owns key row r (rows 0..63 are also the queries) ----
    {
        int r = tid;
        int src_chunk = (r < BSZ) ? c : (c == 0 ? CHUNKS - 1 : c - 1);
        int pos = r & (BSZ - 1);
        int ticker = g_tick[b*TOT + src_chunk*BSZ + pos];
        int t = ticker & (SS - 1);
        tkt[r] = t;
        if (r < BSZ) qtk[r] = ticker;

        float row[DD];
        const float4* kp = (const float4*)(qk + ((size_t)b*SS + t) * DD);
#pragma unroll
        for (int i = 0; i < 16; i++) {
            float4 x = kp[i];
            row[4*i] = x.x; row[4*i+1] = x.y; row[4*i+2] = x.z; row[4*i+3] = x.w;
        }
        float ssq = 0.f;
#pragma unroll
        for (int f = 0; f < DD; f++) ssq = fmaf(row[f], row[f], ssq);
        float nrm = sqrtf(ssq);
        float inv = 1.0f / fmaxf(nrm, 1e-12f);
#pragma unroll
        for (int f = 0; f < DD; f++) Ks[r*KSTR + f] = row[f] * inv;
        if (r < BSZ) {
#pragma unroll
            for (int f = 0; f < DD; f++) Qs[r*QSTR + f] = row[f];
        }

        const float4* vp = (const float4*)(v + ((size_t)b*SS + t) * DD);
#pragma unroll
        for (int i = 0; i < 16; i++) {
            float4 x = vp[i];
            Vs[r*KSTR + 4*i] = x.x; Vs[r*KSTR + 4*i+1] = x.y;
            Vs[r*KSTR + 4*i+2] = x.z; Vs[r*KSTR + 4*i+3] = x.w;
        }
    }
    __syncthreads();

    // ---- phase 1: dots[i,j] = sum_f q[i,f]*k̂[j,f], sequential chain over f
    //      (4 queries interleaved for ILP; per-output rounding unchanged). ----
    {
        int j = tid;
        float kr[DD];
#pragma unroll
        for (int f = 0; f < DD; f++) kr[f] = Ks[j*KSTR + f];
        int tj = tkt[j];
        for (int i0 = 0; i0 < BSZ; i0 += 4) {
            const float* q0 = Qs + (i0+0)*QSTR;
            const float* q1 = Qs + (i0+1)*QSTR;
            const float* q2 = Qs + (i0+2)*QSTR;
            const float* q3 = Qs + (i0+3)*QSTR;
            float s0 = 0.f, s1 = 0.f, s2 = 0.f, s3 = 0.f;
#pragma unroll
            for (int f = 0; f < DD; f++) {
                float kf = kr[f];
                s0 = fmaf(q0[f], kf, s0);
                s1 = fmaf(q1[f], kf, s1);
                s2 = fmaf(q2[f], kf, s2);
                s3 = fmaf(q3[f], kf, s3);
            }
            float dots[4] = {s0, s1, s2, s3};
#pragma unroll
            for (int u = 0; u < 4; u++) {
                int i = i0 + u;
                float val = dots[u] * 0.125f;     // D^-0.5 = 1/8
                if (tkt[i] == tj) val = -1e5f;    // self mask (by position t)
                Sm[i*SSTR + j] = val;
            }
        }
    }
    __syncthreads();

    // ---- phase 2: row lse; probs = exp(dots - lse) ----
    if (tid < BSZ) {
        int i = tid;
        float* row = Sm + i*SSTR;
        float m = -INFINITY;
        for (int j = 0; j < KEYS; j++) m = fmaxf(m, row[j]);
        float s = 0.f;
        for (int j = 0; j < KEYS; j++) s += expf(row[j] - m);
        float lse = m + logf(s);
        for (int j = 0; j < KEYS; j++) row[j] = expf(row[j] - lse);
        g_logits[b*TOT + qtk[i]] = lse;
    }
    __syncthreads();

    // ---- phase 3: PV, sequential over j (matches reference sum order) ----
    {
        int i  = tid & (BSZ - 1);
        int fb = (tid >> 6) * 32;
        float acc[32];
#pragma unroll
        for (int f = 0; f < 32; f++) acc[f] = 0.f;
        for (int j = 0; j < KEYS; j++) {
            float p = Sm[i*SSTR + j];
            const float* vr = Vs + j*KSTR + fb;   // broadcast across lanes
#pragma unroll
            for (int f = 0; f < 32; f++) acc[f] = fmaf(p, vr[f], acc[f]);
        }
        float* op = g_o + ((size_t)b*TOT + qtk[i]) * DD + fb;
#pragma unroll
        for (int f = 0; f < 32; f += 4) {
            float4 x = {acc[f], acc[f+1], acc[f+2], acc[f+3]};
            *(float4*)(op + f) = x;
        }
    }
}

// ---------------- kernel 5: combine hash rounds (elementwise, fp32) ----------
__global__ void k_combine(float* __restrict__ out) {
    int idx = blockIdx.x * blockDim.x + threadIdx.x;  // over B*S*16 (float4 lanes)
    if (idx >= BB*SS*16) return;
    int q  = idx & 15;
    int bt = idx >> 4;            // b*S + t
    int b  = bt >> 12, t = bt & (SS - 1);

    const float* lp = g_logits + b*TOT + t;
    float l[HH];
    float m = -INFINITY;
#pragma unroll
    for (int h = 0; h < HH; h++) { l[h] = lp[h*SS]; m = fmaxf(m, l[h]); }
    float s = 0.f;
#pragma unroll
    for (int h = 0; h < HH; h++) { l[h] = expf(l[h] - m); s += l[h]; }
    float invs = 1.0f / s;

    float4 acc = {0.f, 0.f, 0.f, 0.f};
#pragma unroll
    for (int h = 0; h < HH; h++) {
        const float4* op = (const float4*)(g_o + ((size_t)b*TOT + h*SS + t) * DD) + q;
        float4 x = *op;
        float w = l[h] * invs;
        acc.x = fmaf(w, x.x, acc.x);
        acc.y = fmaf(w, x.y, acc.y);
        acc.z = fmaf(w, x.z, acc.z);
        acc.w = fmaf(w, x.w, acc.w);
    }
    ((float4*)out)[(size_t)bt * 16 + q] = acc;
}

// ---------------- kernel 6: buckets output (2nd tuple element) ---------------
__global__ void k_buckets(float* __restrict__ out) {
    int i = blockIdx.x * blockDim.x + threadIdx.x;
    if (i < BB*TOT) out[i] = (float)g_buckets[i];
}

// ---------------- launcher ---------------------------------------------------
extern "C" void kernel_launch(void* const* d_in, const int* in_sizes, int n_in,
                              void* d_out, int out_size) {
    const float* qk  = (const float*)d_in[0];
    const float* v   = (const float*)d_in[1];
    const float* rot = (const float*)d_in[2];
    float* out = (float*)d_out;

    cudaFuncSetAttribute(k_hash, cudaFuncAttributeMaxDynamicSharedMemorySize,
                         DD*HH*NROT*4);
    cudaFuncSetAttribute(k_attn, cudaFuncAttributeMaxDynamicSharedMemorySize,
                         ATT_SMEM);

    k_zero<<<(BB*TBK + 255) / 256, 256>>>();
    k_hash<<<BB*SS / 256, 256, DD*HH*NROT*4>>>(qk, rot);
    k_scan<<<BB, TBK>>>();
    k_scatter<<<(BB*TBK + 127) / 128, 128>>>();
    dim3 ag(CHUNKS, BB);
    k_attn<<<ag, 128, ATT_SMEM>>>(qk, v);
    k_combine<<<(BB*SS*16 + 255) / 256, 256>>>(out);
    if (out_size >= BB*SS*DD + BB*TOT) {
        k_buckets<<<(BB*TOT + 255) / 256, 256>>>(out + (size_t)BB*SS*DD);
    }
}

// round 5
// speedup vs baseline: 1.4730x; 1.4730x over previous
#include <cuda_runtime.h>
#include <math.h>
#include <stdint.h>

// Problem constants
#define BB 16          // batch
#define SS 4096        // sequence
#define DD 64          // head dim
#define HH 8           // n_hashes
#define NB 64          // buckets per hash
#define NROT 32        // n_buckets/2 rotation outputs
#define TBK 512        // total buckets per batch (HH*NB)
#define CHUNKS 512     // sorted chunks per batch
#define BSZ 64         // bucket/chunk size
#define KEYS 128       // keys per chunk (own + look-back)
#define TOT (HH*SS)    // 32768 sorted entries per batch

// ---- packed f32x2 helpers: each lane is an exact scalar fp32 fma, so a
// ---- per-output sequential chain keeps bit-identical rounding.
__device__ __forceinline__ uint64_t ffma2(uint64_t a, uint64_t b, uint64_t c) {
    uint64_t d;
    asm("fma.rn.f32x2 %0,%1,%2,%3;" : "=l"(d) : "l"(a), "l"(b), "l"(c));
    return d;
}
__device__ __forceinline__ uint64_t pack2(float x) {
    uint64_t r; uint32_t b = __float_as_uint(x);
    asm("mov.b64 %0,{%1,%1};" : "=l"(r) : "r"(b));
    return r;
}
__device__ __forceinline__ void unpack2(uint64_t p, float& a, float& b) {
    uint32_t lo, hi;
    asm("mov.b64 {%0,%1},%2;" : "=r"(lo), "=r"(hi) : "l"(p));
    a = __uint_as_float(lo); b = __uint_as_float(hi);
}

// ---------------- scratch (device globals; no allocs allowed) ----------------
__device__ int   g_buckets[BB*TOT];
__device__ int   g_hist[BB*TBK];
__device__ int   g_off[BB*TBK];
__device__ int   g_tick[BB*TOT];
__device__ float g_logits[BB*TOT];
__device__ float g_o[(size_t)BB*TOT*DD];     // per-hash outputs, 128 MB

// ---------------- kernel 0: zero histogram -----------------------------------
__global__ void k_zero() {
    int i = blockIdx.x * blockDim.x + threadIdx.x;
    if (i < BB*TBK) g_hist[i] = 0;
}

// ---------------- kernel 1: LSH hashing (packed f32x2, chains over f) --------
__global__ void __launch_bounds__(256) k_hash(const float* __restrict__ qk,
                                              const float* __restrict__ rot) {
    extern __shared__ float srot[];          // [D][H][NROT] = 16384 floats
    for (int i = threadIdx.x; i < DD*HH*NROT; i += blockDim.x) srot[i] = rot[i];
    __syncthreads();

    int g = blockIdx.x * blockDim.x + threadIdx.x;  // global token (b*S + t)
    int b = g >> 12;
    int t = g & (SS - 1);

    float q[DD];
    const float4* qp = (const float4*)(qk + (size_t)g * DD);
#pragma unroll
    for (int i = 0; i < 16; i++) {
        float4 x = qp[i];
        q[4*i] = x.x; q[4*i+1] = x.y; q[4*i+2] = x.z; q[4*i+3] = x.w;
    }

    for (int h = 0; h < HH; h++) {
        uint64_t acc[16];
#pragma unroll
        for (int p = 0; p < 16; p++) acc[p] = 0ull;
#pragma unroll 2
        for (int f = 0; f < DD; f++) {
            uint64_t q2 = pack2(q[f]);
            const ulonglong2* rp = (const ulonglong2*)(srot + f*(HH*NROT) + h*NROT);
#pragma unroll
            for (int u = 0; u < 8; u++) {
                ulonglong2 rr = rp[u];                 // broadcast LDS.128
                acc[2*u]   = ffma2(q2, rr.x, acc[2*u]);
                acc[2*u+1] = ffma2(q2, rr.y, acc[2*u+1]);
            }
        }
        float bv = -INFINITY; int bi = 0;
#pragma unroll
        for (int p = 0; p < 16; p++) {
            float d0, d1; unpack2(acc[p], d0, d1);
            int i0 = 2*p;
            if (d0 > bv || (d0 == bv && i0 < bi)) { bv = d0; bi = i0; }
            float n0 = -d0; int m0 = NROT + i0;
            if (n0 > bv || (n0 == bv && m0 < bi)) { bv = n0; bi = m0; }
            int i1 = 2*p + 1;
            if (d1 > bv || (d1 == bv && i1 < bi)) { bv = d1; bi = i1; }
            float n1 = -d1; int m1 = NROT + i1;
            if (n1 > bv || (n1 == bv && m1 < bi)) { bv = n1; bi = m1; }
        }
        int bucket = bi + h * NB;
        g_buckets[b*TOT + h*SS + t] = bucket;
        atomicAdd(&g_hist[b*TBK + bucket], 1);
    }
}

// ---------------- kernel 2: exclusive scan of histogram (per batch) ----------
__global__ void k_scan() {
    __shared__ int s[TBK];
    int b = blockIdx.x, t = threadIdx.x;
    int myv = g_hist[b*TBK + t];
    s[t] = myv;
    __syncthreads();
    for (int o = 1; o < TBK; o <<= 1) {
        int v = (t >= o) ? s[t - o] : 0;
        __syncthreads();
        s[t] += v;
        __syncthreads();
    }
    g_off[b*TBK + t] = s[t] - myv;
}

// ---------------- kernel 3: counting-sort scatter, warp-ballot (stable) ------
__global__ void __launch_bounds__(256) k_scatter() {
    int w = (blockIdx.x * blockDim.x + threadIdx.x) >> 5;  // one warp per bucket
    if (w >= BB*TBK) return;
    int lane = threadIdx.x & 31;
    int b = w / TBK, bucket = w % TBK;
    int h = bucket >> 6;
    const int* bp = g_buckets + b*TOT + h*SS;
    int off = g_off[w];
    int* out = g_tick + b*TOT;
    int base = h * SS;
    for (int t0 = 0; t0 < SS; t0 += 32) {
        int t = t0 + lane;
        bool m = (bp[t] == bucket);
        unsigned msk = __ballot_sync(0xffffffffu, m);
        int pre = __popc(msk & ((1u << lane) - 1));
        if (m) out[off + pre] = base + t;       // ascending t => stable
        off += __popc(msk);
    }
}

// ---------------- kernel 4: chunked attention (256 threads, packed) ----------
// Shared: Qs2 [f][i] f-major (pairs of queries contiguous), Ks[128][65],
//         Vs[128][68] (16B-aligned rows), Sm[64][129], positions/tickers.
#define KSTR 65
#define VSTR 68
#define SSTR 129
#define QS2_SZ (DD*BSZ)
#define KS_SZ  (KEYS*KSTR)
#define VS_SZ  (KEYS*VSTR)
#define SM_SZ  (BSZ*SSTR)
#define ATT_SMEM ((QS2_SZ + KS_SZ + VS_SZ + SM_SZ)*4 + KEYS*4 + BSZ*4)

__global__ void __launch_bounds__(256, 1) k_attn(const float* __restrict__ qk,
                                                 const float* __restrict__ v) {
    extern __shared__ char smraw[];
    float* Qs2 = (float*)smraw;                   // [64 f][64 i], raw q transposed
    float* Ks  = Qs2 + QS2_SZ;                    // normalized k, row-major
    float* Vs  = Ks + KS_SZ;
    float* Sm  = Vs + VS_SZ;                      // dots -> probs
    int*   tkt = (int*)(Sm + SM_SZ);              // key positions (t)
    int*   qtk = tkt + KEYS;                      // query tickers (h*S+t)

    int c = blockIdx.x, b = blockIdx.y;
    int tid = threadIdx.x;

    // ---- load: tid<128 loads K row r (+Q for r<64); tid>=128 loads V row ----
    {
        int r = tid & 127;
        int src_chunk = (r < BSZ) ? c : (c == 0 ? CHUNKS - 1 : c - 1);
        int pos = r & (BSZ - 1);
        int ticker = g_tick[b*TOT + src_chunk*BSZ + pos];
        int t = ticker & (SS - 1);
        if (tid < 128) {
            tkt[r] = t;
            if (r < BSZ) qtk[r] = ticker;
            float row[DD];
            const float4* kp = (const float4*)(qk + ((size_t)b*SS + t) * DD);
#pragma unroll
            for (int i = 0; i < 16; i++) {
                float4 x = kp[i];
                row[4*i] = x.x; row[4*i+1] = x.y; row[4*i+2] = x.z; row[4*i+3] = x.w;
            }
            float ssq = 0.f;
#pragma unroll
            for (int f = 0; f < DD; f++) ssq = fmaf(row[f], row[f], ssq);
            float nrm = sqrtf(ssq);
            float inv = 1.0f / fmaxf(nrm, 1e-12f);
#pragma unroll
            for (int f = 0; f < DD; f++) Ks[r*KSTR + f] = row[f] * inv;
            if (r < BSZ) {
#pragma unroll
                for (int f = 0; f < DD; f++) Qs2[f*BSZ + r] = row[f];
            }
        } else {
            const float4* vp = (const float4*)(v + ((size_t)b*SS + t) * DD);
#pragma unroll
            for (int i = 0; i < 16; i++) {
                float4 x = vp[i];
                Vs[r*VSTR + 4*i]   = x.x; Vs[r*VSTR + 4*i+1] = x.y;
                Vs[r*VSTR + 4*i+2] = x.z; Vs[r*VSTR + 4*i+3] = x.w;
            }
        }
    }
    __syncthreads();

    // ---- phase 1: dots[i,j], sequential chain over f per output.
    //      thread = (key j, query-half qh); 32 query chains packed as 16 pairs.
    {
        int j  = tid & 127;
        int qh = tid >> 7;
        int tj = tkt[j];
        const float* krow = Ks + j*KSTR;
        const float* qcol = Qs2 + qh*32;
        uint64_t acc[16];
#pragma unroll
        for (int p = 0; p < 16; p++) acc[p] = 0ull;
#pragma unroll 2
        for (int f = 0; f < DD; f++) {
            uint64_t k2 = pack2(krow[f]);         // conflict-free (stride 65)
            const ulonglong2* qp2 = (const ulonglong2*)(qcol + f*BSZ);
#pragma unroll
            for (int u = 0; u < 8; u++) {
                ulonglong2 qq = qp2[u];           // broadcast LDS.128
                acc[2*u]   = ffma2(qq.x, k2, acc[2*u]);
                acc[2*u+1] = ffma2(qq.y, k2, acc[2*u+1]);
            }
        }
#pragma unroll
        for (int p = 0; p < 16; p++) {
            float d0, d1; unpack2(acc[p], d0, d1);
            int i0 = qh*32 + 2*p;
            float v0 = d0 * 0.125f; if (tkt[i0]     == tj) v0 = -1e5f;
            float v1 = d1 * 0.125f; if (tkt[i0 + 1] == tj) v1 = -1e5f;
            Sm[i0*SSTR + j]       = v0;
            Sm[(i0 + 1)*SSTR + j] = v1;
        }
    }
    __syncthreads();

    // ---- phase 2: softmax, 4 threads per row (deterministic butterfly) ----
    {
        int i = tid >> 2;
        int cq = tid & 3;
        float* row = Sm + i*SSTR + cq*32;
        float m = -INFINITY;
#pragma unroll
        for (int j = 0; j < 32; j++) m = fmaxf(m, row[j]);
        m = fmaxf(m, __shfl_xor_sync(0xffffffffu, m, 1));
        m = fmaxf(m, __shfl_xor_sync(0xffffffffu, m, 2));
        float s = 0.f;
        for (int j = 0; j < 32; j++) s += expf(row[j] - m);
        s += __shfl_xor_sync(0xffffffffu, s, 1);
        s += __shfl_xor_sync(0xffffffffu, s, 2);
        float lse = m + logf(s);
        for (int j = 0; j < 32; j++) row[j] = expf(row[j] - lse);
        if (cq == 0) g_logits[b*TOT + qtk[i]] = lse;
    }
    __syncthreads();

    // ---- phase 3: PV, sequential chain over j per output (f-pairs packed).
    //      thread = (query i, 16-float quarter of D).
    {
        int i  = tid & 63;
        int fb = (tid >> 6) * 16;
        const float* srow = Sm + i*SSTR;
        uint64_t acc[8];
#pragma unroll
        for (int p = 0; p < 8; p++) acc[p] = 0ull;
#pragma unroll 2
        for (int j = 0; j < KEYS; j++) {
            uint64_t p2 = pack2(srow[j]);         // conflict-free (stride 129)
            const ulonglong2* vp2 = (const ulonglong2*)(Vs + j*VSTR + fb);
#pragma unroll
            for (int u = 0; u < 4; u++) {
                ulonglong2 vv = vp2[u];           // broadcast LDS.128
                acc[2*u]   = ffma2(p2, vv.x, acc[2*u]);
                acc[2*u+1] = ffma2(p2, vv.y, acc[2*u+1]);
            }
        }
        float o[16];
#pragma unroll
        for (int p = 0; p < 8; p++) unpack2(acc[p], o[2*p], o[2*p+1]);
        float* op = g_o + ((size_t)b*TOT + qtk[i]) * DD + fb;
#pragma unroll
        for (int f = 0; f < 16; f += 4) {
            float4 x = {o[f], o[f+1], o[f+2], o[f+3]};
            *(float4*)(op + f) = x;
        }
    }
}

// ---------------- kernel 5: combine hash rounds (elementwise, fp32) ----------
__global__ void k_combine(float* __restrict__ out) {
    int idx = blockIdx.x * blockDim.x + threadIdx.x;  // over B*S*16 (float4 lanes)
    if (idx >= BB*SS*16) return;
    int q  = idx & 15;
    int bt = idx >> 4;            // b*S + t
    int b  = bt >> 12, t = bt & (SS - 1);

    const float* lp = g_logits + b*TOT + t;
    float l[HH];
    float m = -INFINITY;
#pragma unroll
    for (int h = 0; h < HH; h++) { l[h] = lp[h*SS]; m = fmaxf(m, l[h]); }
    float s = 0.f;
#pragma unroll
    for (int h = 0; h < HH; h++) { l[h] = expf(l[h] - m); s += l[h]; }
    float invs = 1.0f / s;

    float4 acc = {0.f, 0.f, 0.f, 0.f};
#pragma unroll
    for (int h = 0; h < HH; h++) {
        const float4* op = (const float4*)(g_o + ((size_t)b*TOT + h*SS + t) * DD) + q;
        float4 x = *op;
        float w = l[h] * invs;
        acc.x = fmaf(w, x.x, acc.x);
        acc.y = fmaf(w, x.y, acc.y);
        acc.z = fmaf(w, x.z, acc.z);
        acc.w = fmaf(w, x.w, acc.w);
    }
    ((float4*)out)[(size_t)bt * 16 + q] = acc;
}

// ---------------- kernel 6: buckets output (2nd tuple element) ---------------
__global__ void k_buckets(float* __restrict__ out) {
    int i = blockIdx.x * blockDim.x + threadIdx.x;
    if (i < BB*TOT) out[i] = (float)g_buckets[i];
}

// ---------------- launcher ---------------------------------------------------
extern "C" void kernel_launch(void* const* d_in, const int* in_sizes, int n_in,
                              void* d_out, int out_size) {
    const float* qk  = (const float*)d_in[0];
    const float* v   = (const float*)d_in[1];
    const float* rot = (const float*)d_in[2];
    float* out = (float*)d_out;

    cudaFuncSetAttribute(k_hash, cudaFuncAttributeMaxDynamicSharedMemorySize,
                         DD*HH*NROT*4);
    cudaFuncSetAttribute(k_attn, cudaFuncAttributeMaxDynamicSharedMemorySize,
                         ATT_SMEM);

    k_zero<<<(BB*TBK + 255) / 256, 256>>>();
    k_hash<<<BB*SS / 256, 256, DD*HH*NROT*4>>>(qk, rot);
    k_scan<<<BB, TBK>>>();
    k_scatter<<<(BB*TBK*32 + 255) / 256, 256>>>();
    dim3 ag(CHUNKS, BB);
    k_attn<<<ag, 256, ATT_SMEM>>>(qk, v);
    k_combine<<<(BB*SS*16 + 255) / 256, 256>>>(out);
    if (out_size >= BB*SS*DD + BB*TOT) {
        k_buckets<<<(BB*TOT + 255) / 256, 256>>>(out + (size_t)BB*SS*DD);
    }
}